// round 10
// baseline (speedup 1.0000x reference)
#include <cuda_runtime.h>
#include <cuda_bf16.h>
#include <mma.h>
#include <math.h>
#include <stdint.h>

using namespace nvcuda;

#define N_NODES 40000
#define N_PAD   40064          // 313 * 128
#define E_EDGES 640000
#define IN_DIM  256
#define H_DIM   128
#define C_DIM   64
#define L_LAYERS 4
#define ALPHA   0.5f
#define SCAN_B  1024
#define SCAN_NB 40

// ======================= device scratch (no allocations allowed) =======================
__device__ float g_h[N_PAD * H_DIM];                 // current features (fp32)
__device__ __nv_bfloat16 g_xh[N_PAD * IN_DIM], g_xl[N_PAD * IN_DIM];
__device__ __nv_bfloat16 g_f0h[N_PAD * H_DIM], g_f0l[N_PAD * H_DIM];
__device__ __nv_bfloat16 g_fth[N_PAD * H_DIM], g_ftl[N_PAD * H_DIM];
__device__ __nv_bfloat16 g_hh[N_PAD * H_DIM],  g_hl[N_PAD * H_DIM];
// transposed + split weights ([N][K], K contiguous). Layer weights: M = beta*W + (1-beta)*I.
__device__ __nv_bfloat16 g_w1Th[H_DIM * IN_DIM], g_w1Tl[H_DIM * IN_DIM];
__device__ __nv_bfloat16 g_WTh[L_LAYERS * 2 * H_DIM * H_DIM], g_WTl[L_LAYERS * 2 * H_DIM * H_DIM];
__device__ __nv_bfloat16 g_w2Th[C_DIM * H_DIM], g_w2Tl[C_DIM * H_DIM];
// CSR
__device__ float g_norm_s[N_NODES], g_norm_d[N_NODES];
__device__ int   g_cnt_in[N_NODES], g_cnt_out[N_NODES], g_fill[N_NODES];
__device__ int   g_rowptr[N_NODES + 1];
__device__ int   g_bsum[SCAN_NB];
__device__ int   g_csr_src[E_EDGES];
__device__ float g_csr_w[E_EDGES];

// ======================= init =======================
__global__ void init_kernel() {
    int i = blockIdx.x * blockDim.x + threadIdx.x;
    const __nv_bfloat16 z = __float2bfloat16_rn(0.f);
    if (i < N_NODES) { g_cnt_in[i] = 0; g_cnt_out[i] = 0; }
    if (i < (N_PAD - N_NODES) * IN_DIM) {
        g_xh[N_NODES * IN_DIM + i] = z;
        g_xl[N_NODES * IN_DIM + i] = z;
    }
    if (i < (N_PAD - N_NODES) * H_DIM) {
        int o = N_NODES * H_DIM + i;
        g_f0h[o] = z; g_f0l[o] = z;
        g_fth[o] = z; g_ftl[o] = z;
        g_hh[o]  = z; g_hl[o]  = z;
    }
}

// ======================= prep: degree count + convert x + split weights =======================
__global__ void prep_kernel(const int* __restrict__ src, const int* __restrict__ dst,
                            const float* __restrict__ x,
                            const float* __restrict__ fc1_w,
                            const float* __restrict__ W1,
                            const float* __restrict__ W2,
                            const float* __restrict__ fc2_w) {
    int i = blockIdx.x * blockDim.x + threadIdx.x;
    if (i < E_EDGES) {
        atomicAdd(&g_cnt_in[dst[i]], 1);
        atomicAdd(&g_cnt_out[src[i]], 1);
    }
    if (i < N_NODES * IN_DIM / 4) {
        float4 v = ((const float4*)x)[i];
        __nv_bfloat16 b0 = __float2bfloat16_rn(v.x), b1 = __float2bfloat16_rn(v.y);
        __nv_bfloat16 b2 = __float2bfloat16_rn(v.z), b3 = __float2bfloat16_rn(v.w);
        __nv_bfloat162 h01; h01.x = b0; h01.y = b1;
        __nv_bfloat162 h23; h23.x = b2; h23.y = b3;
        __nv_bfloat162 l01; l01.x = __float2bfloat16_rn(v.x - __bfloat162float(b0));
                            l01.y = __float2bfloat16_rn(v.y - __bfloat162float(b1));
        __nv_bfloat162 l23; l23.x = __float2bfloat16_rn(v.z - __bfloat162float(b2));
                            l23.y = __float2bfloat16_rn(v.w - __bfloat162float(b3));
        size_t base = (size_t)i * 4;
        *(__nv_bfloat162*)(g_xh + base)     = h01;
        *(__nv_bfloat162*)(g_xh + base + 2) = h23;
        *(__nv_bfloat162*)(g_xl + base)     = l01;
        *(__nv_bfloat162*)(g_xl + base + 2) = l23;
    }
    if (i < H_DIM * IN_DIM) {
        int n = i / IN_DIM, k = i % IN_DIM;
        float w = fc1_w[k * H_DIM + n];
        __nv_bfloat16 h = __float2bfloat16_rn(w);
        g_w1Th[i] = h;
        g_w1Tl[i] = __float2bfloat16_rn(w - __bfloat162float(h));
    }
    if (i < L_LAYERS * 2 * H_DIM * H_DIM) {
        int l = i / (2 * H_DIM * H_DIM);
        int rem = i % (2 * H_DIM * H_DIM);
        int g = rem / (H_DIM * H_DIM);
        int nk = rem % (H_DIM * H_DIM);
        int n = nk / H_DIM, k = nk % H_DIM;
        float beta = logf(1.0f / (float)(l + 1) + 1.0f);
        const float* srcw = g ? W2 : W1;
        float w = beta * srcw[(size_t)l * H_DIM * H_DIM + k * H_DIM + n]
                + ((n == k) ? (1.0f - beta) : 0.0f);
        __nv_bfloat16 h = __float2bfloat16_rn(w);
        g_WTh[i] = h;
        g_WTl[i] = __float2bfloat16_rn(w - __bfloat162float(h));
    }
    if (i < C_DIM * H_DIM) {
        int n = i / H_DIM, k = i % H_DIM;
        float w = fc2_w[k * C_DIM + n];
        __nv_bfloat16 h = __float2bfloat16_rn(w);
        g_w2Th[i] = h;
        g_w2Tl[i] = __float2bfloat16_rn(w - __bfloat162float(h));
    }
}

// ======================= scan =======================
__global__ void scan1_kernel() {
    __shared__ int sh[SCAN_B];
    int tid = threadIdx.x;
    int gid = blockIdx.x * SCAN_B + tid;
    int v = (gid < N_NODES) ? g_cnt_in[gid] : 0;
    sh[tid] = v;
    __syncthreads();
    for (int off = 1; off < SCAN_B; off <<= 1) {
        int t = (tid >= off) ? sh[tid - off] : 0;
        __syncthreads();
        sh[tid] += t;
        __syncthreads();
    }
    if (gid < N_NODES) g_rowptr[gid] = sh[tid] - v;
    if (tid == SCAN_B - 1) g_bsum[blockIdx.x] = sh[tid];
}

__global__ void scan23_kernel() {
    __shared__ int sh[64];
    int tid = threadIdx.x;
    int v = (tid < SCAN_NB) ? g_bsum[tid] : 0;
    if (tid < 64) sh[tid] = v;
    __syncthreads();
    for (int off = 1; off < 64; off <<= 1) {
        int u = (tid < 64 && tid >= off) ? sh[tid - off] : 0;
        __syncthreads();
        if (tid < 64) sh[tid] += u;
        __syncthreads();
    }
    int gid = blockIdx.x * blockDim.x + tid;
    if (gid < N_NODES) {
        int b = gid >> 10;
        int rp = g_rowptr[gid] + sh[b] - g_bsum[b];
        g_rowptr[gid] = rp;
        g_fill[gid] = rp;
        g_norm_s[gid] = rsqrtf(fmaxf((float)g_cnt_out[gid], 1.f));
        g_norm_d[gid] = rsqrtf(fmaxf((float)g_cnt_in[gid], 1.f));
    }
    if (gid == 0) g_rowptr[N_NODES] = E_EDGES;
}

__global__ void fill_kernel(const int* __restrict__ src, const int* __restrict__ dst) {
    int e = blockIdx.x * blockDim.x + threadIdx.x;
    if (e < E_EDGES) {
        int d = dst[e], s = src[e];
        int pos = atomicAdd(&g_fill[d], 1);
        g_csr_src[pos] = s;
        g_csr_w[pos] = g_norm_s[s];
    }
}

// ---------------- gather SpMM (unchanged from R7) ----------------
__global__ void gather_kernel() {
    int gw = (blockIdx.x * blockDim.x + threadIdx.x) >> 5;
    int lane = threadIdx.x & 31;
    if (gw >= N_NODES) return;
    int beg = g_rowptr[gw];
    int end = g_rowptr[gw + 1];
    float4 acc = make_float4(0.f, 0.f, 0.f, 0.f);
    for (int base = beg; base < end; base += 32) {
        int e = base + lane;
        int s = 0; float wgt = 0.f;
        if (e < end) { s = g_csr_src[e]; wgt = g_csr_w[e]; }
        #pragma unroll
        for (int c = 0; c < 4; ++c) {
            if (base + c * 8 >= end) break;   // warp-uniform
            #pragma unroll
            for (int j = 0; j < 8; ++j) {
                int jj = c * 8 + j;
                int   sj = __shfl_sync(0xffffffffu, s, jj);
                float wj = __shfl_sync(0xffffffffu, wgt, jj);
                float4 v = __ldg((const float4*)(g_h + (size_t)sj * H_DIM) + lane);
                acc.x += v.x * wj; acc.y += v.y * wj;
                acc.z += v.z * wj; acc.w += v.w * wj;
            }
        }
    }
    float sc = (1.f - ALPHA) * g_norm_d[gw];
    float f0 = acc.x * sc, f1 = acc.y * sc, f2 = acc.z * sc, f3 = acc.w * sc;
    __nv_bfloat16 b0 = __float2bfloat16_rn(f0), b1 = __float2bfloat16_rn(f1);
    __nv_bfloat16 b2 = __float2bfloat16_rn(f2), b3 = __float2bfloat16_rn(f3);
    size_t base = (size_t)gw * H_DIM + lane * 4;
    __nv_bfloat162 h01; h01.x = b0; h01.y = b1;
    __nv_bfloat162 h23; h23.x = b2; h23.y = b3;
    *(__nv_bfloat162*)(g_fth + base)     = h01;
    *(__nv_bfloat162*)(g_fth + base + 2) = h23;
    __nv_bfloat162 l01; l01.x = __float2bfloat16_rn(f0 - __bfloat162float(b0));
                        l01.y = __float2bfloat16_rn(f1 - __bfloat162float(b1));
    __nv_bfloat162 l23; l23.x = __float2bfloat16_rn(f2 - __bfloat162float(b2));
                        l23.y = __float2bfloat16_rn(f3 - __bfloat162float(b3));
    *(__nv_bfloat162*)(g_ftl + base)     = l01;
    *(__nv_bfloat162*)(g_ftl + base + 2) = l23;
}

// ======================= WMMA bf16-split GEMM, 128x64 CTA tile (2 CTAs/SM) =======================
// MODE 0: acc = x@fc1_w  -> h = relu(acc+b); f0 = split(ALPHA*h)
// MODE 1: acc = feat@M1 + f0@M2 -> h = relu(acc + bgc + h)
// MODE 2: acc = h@fc2_w -> out = acc + b
// grid = (NDIM/64, 313). 8 warps: 4 row-groups x 2 col-groups, warp tile 32x32.
template <int MODE>
__global__ void __launch_bounds__(256) gemm_tc(const float* __restrict__ bias,
                                               float* __restrict__ Cout,
                                               int layer, int writeH) {
    constexpr int NDIM  = (MODE == 2) ? 64 : 128;   // full B rows
    constexpr int KFULL = (MODE == 0) ? 256 : 128;
    constexpr int NPROD = (MODE == 1) ? 6 : 3;
    constexpr int KC = 64;
    constexpr int TN = 64;                           // CTA col-tile
    constexpr int LDA = 72, LDB = 72, LDST = 68;

    // union: A tile (128*72*2=18432) + B tile (64*72*2=9216) = 27648B  vs  stage 128*68*4 = 34816B
    __shared__ __align__(16) unsigned char smem[128 * LDST * 4];
    __nv_bfloat16* sA = (__nv_bfloat16*)smem;
    __nv_bfloat16* sB = sA + 128 * LDA;
    float* stage = (float*)smem;

    const int tid = threadIdx.x;
    const int wid = tid >> 5;
    const int wr  = wid & 3;            // 0..3: 32-row group
    const int wc  = wid >> 2;           // 0..1: 32-col group
    const int colBase = blockIdx.x * TN;
    const int rowBase = blockIdx.y * 128;
    const bool fullTile = (rowBase + 128 <= N_NODES);

    wmma::fragment<wmma::accumulator, 16, 16, 16, float> acc[2][2];
    #pragma unroll
    for (int i = 0; i < 2; ++i)
        #pragma unroll
        for (int j = 0; j < 2; ++j)
            wmma::fill_fragment(acc[i][j], 0.f);

    for (int prod = 0; prod < NPROD; ++prod) {
        const __nv_bfloat16 *Ap, *Bp;
        if (MODE == 0) {
            Ap = (prod == 1) ? g_xl : g_xh;
            Bp = (prod == 2) ? g_w1Tl : g_w1Th;
        } else if (MODE == 1) {
            int g = prod / 3, q = prod % 3;
            Ap = g ? ((q == 1) ? g_f0l : g_f0h) : ((q == 1) ? g_ftl : g_fth);
            size_t wo = (size_t)(layer * 2 + g) * H_DIM * H_DIM;
            Bp = (q == 2) ? (g_WTl + wo) : (g_WTh + wo);
        } else {
            Ap = (prod == 1) ? g_hl : g_hh;
            Bp = (prod == 2) ? g_w2Tl : g_w2Th;
        }
        Bp += (size_t)colBase * KFULL;   // this CTA's 64 B-rows

        for (int kb = 0; kb < KFULL; kb += KC) {
            __syncthreads();
            // A tile: 128 rows x 64 bf16
            #pragma unroll
            for (int i = tid; i < 128 * 8; i += 256) {
                int row = i >> 3, c8 = i & 7;
                *(uint4*)&sA[row * LDA + c8 * 8] =
                    *(const uint4*)(Ap + (size_t)(rowBase + row) * KFULL + kb + c8 * 8);
            }
            // B tile: 64 rows x 64 bf16
            #pragma unroll
            for (int i = tid; i < TN * 8; i += 256) {
                int row = i >> 3, c8 = i & 7;
                *(uint4*)&sB[row * LDB + c8 * 8] =
                    *(const uint4*)(Bp + (size_t)row * KFULL + kb + c8 * 8);
            }
            __syncthreads();
            #pragma unroll
            for (int kk = 0; kk < KC / 16; ++kk) {
                wmma::fragment<wmma::matrix_a, 16, 16, 16, __nv_bfloat16, wmma::row_major> af[2];
                wmma::fragment<wmma::matrix_b, 16, 16, 16, __nv_bfloat16, wmma::col_major> bf[2];
                #pragma unroll
                for (int i = 0; i < 2; ++i)
                    wmma::load_matrix_sync(af[i], &sA[(wr * 32 + i * 16) * LDA + kk * 16], LDA);
                #pragma unroll
                for (int j = 0; j < 2; ++j)
                    wmma::load_matrix_sync(bf[j], &sB[(wc * 32 + j * 16) * LDB + kk * 16], LDB);
                #pragma unroll
                for (int i = 0; i < 2; ++i)
                    #pragma unroll
                    for (int j = 0; j < 2; ++j)
                        wmma::mma_sync(acc[i][j], af[i], bf[j], acc[i][j]);
            }
        }
    }

    // epilogue: single 64-col pass through fp32 smem stage
    __syncthreads();
    #pragma unroll
    for (int i = 0; i < 2; ++i)
        #pragma unroll
        for (int j = 0; j < 2; ++j)
            wmma::store_matrix_sync(&stage[(wr * 32 + i * 16) * LDST + wc * 32 + j * 16],
                                    acc[i][j], LDST, wmma::mem_row_major);
    __syncthreads();
    for (int i = tid; i < 128 * 64; i += 256) {
        int row = i >> 6, c = i & 63;
        int r = rowBase + row, col = colBase + c;
        if (!fullTile && r >= N_NODES) continue;
        float a = stage[row * LDST + c];
        if (MODE == 0) {
            float v = fmaxf(a + bias[col], 0.f);
            int idx = r * H_DIM + col;
            g_h[idx] = v;
            float f0 = ALPHA * v;
            __nv_bfloat16 h = __float2bfloat16_rn(f0);
            g_f0h[idx] = h;
            g_f0l[idx] = __float2bfloat16_rn(f0 - __bfloat162float(h));
        } else if (MODE == 1) {
            int idx = r * H_DIM + col;
            float v = fmaxf(a + bias[col] + g_h[idx], 0.f);
            g_h[idx] = v;
            if (writeH) {
                __nv_bfloat16 h = __float2bfloat16_rn(v);
                g_hh[idx] = h;
                g_hl[idx] = __float2bfloat16_rn(v - __bfloat162float(h));
            }
        } else {
            Cout[(size_t)r * C_DIM + col] = a + bias[col];
        }
    }
}

// ======================= launch (R7 order) =======================
extern "C" void kernel_launch(void* const* d_in, const int* in_sizes, int n_in,
                              void* d_out, int out_size) {
    const float* x     = (const float*)d_in[0];
    const float* fc1_w = (const float*)d_in[1];
    const float* fc1_b = (const float*)d_in[2];
    const float* W1    = (const float*)d_in[3];
    const float* W2    = (const float*)d_in[4];
    const float* bgc   = (const float*)d_in[5];
    const float* fc2_w = (const float*)d_in[6];
    const float* fc2_b = (const float*)d_in[7];
    const int*   src   = (const int*)d_in[8];
    const int*   dst   = (const int*)d_in[9];
    float*       out   = (float*)d_out;

    const int TPB = 256;
    const int nodeBlocks = (N_NODES + TPB - 1) / TPB;
    const int edgeBlocks = (E_EDGES + TPB - 1) / TPB;
    const int prepBlocks = (N_NODES * IN_DIM / 4 + TPB - 1) / TPB;
    const int TILES = N_PAD / 128;   // 313

    init_kernel<<<nodeBlocks, TPB>>>();
    prep_kernel<<<prepBlocks, TPB>>>(src, dst, x, fc1_w, W1, W2, fc2_w);
    scan1_kernel<<<SCAN_NB, SCAN_B>>>();
    scan23_kernel<<<nodeBlocks, TPB>>>();
    fill_kernel<<<edgeBlocks, TPB>>>(src, dst);

    // fc1: 2 column tiles x 313 row tiles
    gemm_tc<0><<<dim3(2, TILES), 256>>>(fc1_b, nullptr, 0, 0);

    const int gatherBlocks = (N_NODES * 32 + TPB - 1) / TPB;
    for (int l = 0; l < L_LAYERS; ++l) {
        gather_kernel<<<gatherBlocks, TPB>>>();
        gemm_tc<1><<<dim3(2, TILES), 256>>>(bgc + (size_t)l * H_DIM, nullptr, l,
                                            (l == L_LAYERS - 1) ? 1 : 0);
    }

    gemm_tc<2><<<dim3(1, TILES), 256>>>(fc2_b, out, 0, 0);
}

// round 11
// speedup vs baseline: 1.3531x; 1.3531x over previous
#include <cuda_runtime.h>
#include <cuda_bf16.h>
#include <mma.h>
#include <math.h>
#include <stdint.h>

using namespace nvcuda;

#define N_NODES 40000
#define N_PAD   40064          // 313 * 128
#define E_EDGES 640000
#define IN_DIM  256
#define H_DIM   128
#define C_DIM   64
#define L_LAYERS 4
#define ALPHA   0.5f
#define SCAN_B  1024
#define SCAN_NB 40

// ======================= device scratch (no allocations allowed) =======================
__device__ float g_h[N_PAD * H_DIM];                 // current features (fp32)
__device__ __nv_bfloat16 g_xh[N_PAD * IN_DIM], g_xl[N_PAD * IN_DIM];
__device__ __nv_bfloat16 g_f0h[N_PAD * H_DIM], g_f0l[N_PAD * H_DIM];
__device__ __nv_bfloat16 g_fth[N_PAD * H_DIM], g_ftl[N_PAD * H_DIM];
// transposed + split weights ([N][K], K contiguous). Layer weights: M = beta*W + (1-beta)*I.
__device__ __nv_bfloat16 g_w1Th[H_DIM * IN_DIM], g_w1Tl[H_DIM * IN_DIM];
__device__ __nv_bfloat16 g_WTh[L_LAYERS * 2 * H_DIM * H_DIM], g_WTl[L_LAYERS * 2 * H_DIM * H_DIM];
__device__ __nv_bfloat16 g_w2Th[C_DIM * H_DIM], g_w2Tl[C_DIM * H_DIM];
// CSR
__device__ float g_norm_s[N_NODES], g_norm_d[N_NODES];
__device__ int   g_cnt_in[N_NODES], g_cnt_out[N_NODES], g_fill[N_NODES];
__device__ int   g_rowptr[N_NODES + 1];
__device__ int   g_bsum[SCAN_NB];
__device__ int   g_csr_src[E_EDGES];
__device__ float g_csr_w[E_EDGES];

// ======================= kernel: init (counters + pad regions) =======================
__global__ void init_kernel() {
    int i = blockIdx.x * blockDim.x + threadIdx.x;
    const __nv_bfloat16 z = __float2bfloat16_rn(0.f);
    if (i < N_NODES) { g_cnt_in[i] = 0; g_cnt_out[i] = 0; }
    if (i < (N_PAD - N_NODES) * IN_DIM) {
        g_xh[N_NODES * IN_DIM + i] = z;
        g_xl[N_NODES * IN_DIM + i] = z;
    }
    if (i < (N_PAD - N_NODES) * H_DIM) {
        int o = N_NODES * H_DIM + i;
        g_f0h[o] = z; g_f0l[o] = z;
        g_fth[o] = z; g_ftl[o] = z;
        g_h[o] = 0.f;                     // fc2 reads g_h pad rows
    }
}

// ======================= prep: degree count + convert x + split weights =======================
__global__ void prep_kernel(const int* __restrict__ src, const int* __restrict__ dst,
                            const float* __restrict__ x,
                            const float* __restrict__ fc1_w,
                            const float* __restrict__ W1,
                            const float* __restrict__ W2,
                            const float* __restrict__ fc2_w) {
    int i = blockIdx.x * blockDim.x + threadIdx.x;
    if (i < E_EDGES) {
        atomicAdd(&g_cnt_in[dst[i]], 1);
        atomicAdd(&g_cnt_out[src[i]], 1);
    }
    if (i < N_NODES * IN_DIM / 4) {
        float4 v = ((const float4*)x)[i];
        __nv_bfloat16 b0 = __float2bfloat16_rn(v.x), b1 = __float2bfloat16_rn(v.y);
        __nv_bfloat16 b2 = __float2bfloat16_rn(v.z), b3 = __float2bfloat16_rn(v.w);
        __nv_bfloat162 h01; h01.x = b0; h01.y = b1;
        __nv_bfloat162 h23; h23.x = b2; h23.y = b3;
        __nv_bfloat162 l01; l01.x = __float2bfloat16_rn(v.x - __bfloat162float(b0));
                            l01.y = __float2bfloat16_rn(v.y - __bfloat162float(b1));
        __nv_bfloat162 l23; l23.x = __float2bfloat16_rn(v.z - __bfloat162float(b2));
                            l23.y = __float2bfloat16_rn(v.w - __bfloat162float(b3));
        size_t base = (size_t)i * 4;
        *(__nv_bfloat162*)(g_xh + base)     = h01;
        *(__nv_bfloat162*)(g_xh + base + 2) = h23;
        *(__nv_bfloat162*)(g_xl + base)     = l01;
        *(__nv_bfloat162*)(g_xl + base + 2) = l23;
    }
    if (i < H_DIM * IN_DIM) {
        int n = i / IN_DIM, k = i % IN_DIM;
        float w = fc1_w[k * H_DIM + n];
        __nv_bfloat16 h = __float2bfloat16_rn(w);
        g_w1Th[i] = h;
        g_w1Tl[i] = __float2bfloat16_rn(w - __bfloat162float(h));
    }
    if (i < L_LAYERS * 2 * H_DIM * H_DIM) {
        int l = i / (2 * H_DIM * H_DIM);
        int rem = i % (2 * H_DIM * H_DIM);
        int g = rem / (H_DIM * H_DIM);
        int nk = rem % (H_DIM * H_DIM);
        int n = nk / H_DIM, k = nk % H_DIM;
        float beta = logf(1.0f / (float)(l + 1) + 1.0f);
        const float* srcw = g ? W2 : W1;
        float w = beta * srcw[(size_t)l * H_DIM * H_DIM + k * H_DIM + n]
                + ((n == k) ? (1.0f - beta) : 0.0f);
        __nv_bfloat16 h = __float2bfloat16_rn(w);
        g_WTh[i] = h;
        g_WTl[i] = __float2bfloat16_rn(w - __bfloat162float(h));
    }
    if (i < C_DIM * H_DIM) {
        int n = i / H_DIM, k = i % H_DIM;
        float w = fc2_w[k * C_DIM + n];
        __nv_bfloat16 h = __float2bfloat16_rn(w);
        g_w2Th[i] = h;
        g_w2Tl[i] = __float2bfloat16_rn(w - __bfloat162float(h));
    }
}

// ======================= scan =======================
__global__ void scan1_kernel() {
    __shared__ int sh[SCAN_B];
    int tid = threadIdx.x;
    int gid = blockIdx.x * SCAN_B + tid;
    int v = (gid < N_NODES) ? g_cnt_in[gid] : 0;
    sh[tid] = v;
    __syncthreads();
    for (int off = 1; off < SCAN_B; off <<= 1) {
        int t = (tid >= off) ? sh[tid - off] : 0;
        __syncthreads();
        sh[tid] += t;
        __syncthreads();
    }
    if (gid < N_NODES) g_rowptr[gid] = sh[tid] - v;
    if (tid == SCAN_B - 1) g_bsum[blockIdx.x] = sh[tid];
}

__global__ void scan23_kernel() {
    __shared__ int sh[64];
    int tid = threadIdx.x;
    int v = (tid < SCAN_NB) ? g_bsum[tid] : 0;
    if (tid < 64) sh[tid] = v;
    __syncthreads();
    for (int off = 1; off < 64; off <<= 1) {
        int u = (tid < 64 && tid >= off) ? sh[tid - off] : 0;
        __syncthreads();
        if (tid < 64) sh[tid] += u;
        __syncthreads();
    }
    int gid = blockIdx.x * blockDim.x + tid;
    if (gid < N_NODES) {
        int b = gid >> 10;
        int rp = g_rowptr[gid] + sh[b] - g_bsum[b];
        g_rowptr[gid] = rp;
        g_fill[gid] = rp;
        g_norm_s[gid] = rsqrtf(fmaxf((float)g_cnt_out[gid], 1.f));
        g_norm_d[gid] = rsqrtf(fmaxf((float)g_cnt_in[gid], 1.f));
    }
    if (gid == 0) g_rowptr[N_NODES] = E_EDGES;
}

__global__ void fill_kernel(const int* __restrict__ src, const int* __restrict__ dst) {
    int e = blockIdx.x * blockDim.x + threadIdx.x;
    if (e < E_EDGES) {
        int d = dst[e], s = src[e];
        int pos = atomicAdd(&g_fill[d], 1);
        g_csr_src[pos] = s;
        g_csr_w[pos] = g_norm_s[s];
    }
}

// ---------------- gather SpMM: one warp per dst row; 8-wide unrolled sub-chunks ----------------
__global__ void gather_kernel() {
    int gw = (blockIdx.x * blockDim.x + threadIdx.x) >> 5;
    int lane = threadIdx.x & 31;
    if (gw >= N_NODES) return;
    int beg = g_rowptr[gw];
    int end = g_rowptr[gw + 1];
    float4 acc = make_float4(0.f, 0.f, 0.f, 0.f);
    for (int base = beg; base < end; base += 32) {
        int e = base + lane;
        int s = 0; float wgt = 0.f;
        if (e < end) { s = g_csr_src[e]; wgt = g_csr_w[e]; }
        #pragma unroll
        for (int c = 0; c < 4; ++c) {
            if (base + c * 8 >= end) break;   // warp-uniform
            #pragma unroll
            for (int j = 0; j < 8; ++j) {
                int jj = c * 8 + j;
                int   sj = __shfl_sync(0xffffffffu, s, jj);
                float wj = __shfl_sync(0xffffffffu, wgt, jj);
                float4 v = __ldg((const float4*)(g_h + (size_t)sj * H_DIM) + lane);
                acc.x += v.x * wj; acc.y += v.y * wj;
                acc.z += v.z * wj; acc.w += v.w * wj;
            }
        }
    }
    float sc = (1.f - ALPHA) * g_norm_d[gw];
    float f0 = acc.x * sc, f1 = acc.y * sc, f2 = acc.z * sc, f3 = acc.w * sc;
    __nv_bfloat16 b0 = __float2bfloat16_rn(f0), b1 = __float2bfloat16_rn(f1);
    __nv_bfloat16 b2 = __float2bfloat16_rn(f2), b3 = __float2bfloat16_rn(f3);
    size_t base = (size_t)gw * H_DIM + lane * 4;
    __nv_bfloat162 h01; h01.x = b0; h01.y = b1;
    __nv_bfloat162 h23; h23.x = b2; h23.y = b3;
    *(__nv_bfloat162*)(g_fth + base)     = h01;
    *(__nv_bfloat162*)(g_fth + base + 2) = h23;
    __nv_bfloat162 l01; l01.x = __float2bfloat16_rn(f0 - __bfloat162float(b0));
                        l01.y = __float2bfloat16_rn(f1 - __bfloat162float(b1));
    __nv_bfloat162 l23; l23.x = __float2bfloat16_rn(f2 - __bfloat162float(b2));
                        l23.y = __float2bfloat16_rn(f3 - __bfloat162float(b3));
    *(__nv_bfloat162*)(g_ftl + base)     = l01;
    *(__nv_bfloat162*)(g_ftl + base + 2) = l23;
}

// ======================= WMMA bf16-split GEMM (R7 structure, MODE 0/1) =======================
// MODE 0: acc = x@fc1_w  -> h = relu(acc+b); f0 = split(ALPHA*h)
// MODE 1: acc = feat@M1 + f0@M2 -> h = relu(acc + bgc + h)
template <int MODE>
__global__ void __launch_bounds__(256) gemm_tc(const float* __restrict__ bias,
                                               int layer) {
    constexpr int NDIM  = 128;
    constexpr int KFULL = (MODE == 0) ? 256 : 128;
    constexpr int NPROD = (MODE == 1) ? 6 : 3;
    constexpr int KC = 64;
    constexpr int LDA = 72, LDB = 72, LDST = 68;
    constexpr int WN = NDIM / 2;
    constexpr int FN = WN / 16;

    __shared__ __align__(16) unsigned char smem[128 * LDA * 2 + 128 * LDB * 2];
    __nv_bfloat16* sA = (__nv_bfloat16*)smem;
    __nv_bfloat16* sB = sA + 128 * LDA;
    float* stage = (float*)smem;

    const int tid = threadIdx.x;
    const int wid = tid >> 5;
    const int wr  = wid & 3;
    const int wc  = wid >> 2;
    const int rowBase = blockIdx.x * 128;
    const bool fullTile = (rowBase + 128 <= N_NODES);

    wmma::fragment<wmma::accumulator, 16, 16, 16, float> acc[2][FN];
    #pragma unroll
    for (int i = 0; i < 2; ++i)
        #pragma unroll
        for (int j = 0; j < FN; ++j)
            wmma::fill_fragment(acc[i][j], 0.f);

    for (int prod = 0; prod < NPROD; ++prod) {
        const __nv_bfloat16 *Ap, *Bp;
        if (MODE == 0) {
            Ap = (prod == 1) ? g_xl : g_xh;
            Bp = (prod == 2) ? g_w1Tl : g_w1Th;
        } else {
            int g = prod / 3, q = prod % 3;
            Ap = g ? ((q == 1) ? g_f0l : g_f0h) : ((q == 1) ? g_ftl : g_fth);
            size_t wo = (size_t)(layer * 2 + g) * H_DIM * H_DIM;
            Bp = (q == 2) ? (g_WTl + wo) : (g_WTh + wo);
        }
        for (int kb = 0; kb < KFULL; kb += KC) {
            __syncthreads();
            #pragma unroll
            for (int i = tid; i < 128 * 8; i += 256) {
                int row = i >> 3, c8 = i & 7;
                *(uint4*)&sA[row * LDA + c8 * 8] =
                    *(const uint4*)(Ap + (size_t)(rowBase + row) * KFULL + kb + c8 * 8);
            }
            #pragma unroll
            for (int i = tid; i < NDIM * 8; i += 256) {
                int row = i >> 3, c8 = i & 7;
                *(uint4*)&sB[row * LDB + c8 * 8] =
                    *(const uint4*)(Bp + (size_t)row * KFULL + kb + c8 * 8);
            }
            __syncthreads();
            #pragma unroll
            for (int kk = 0; kk < KC / 16; ++kk) {
                wmma::fragment<wmma::matrix_a, 16, 16, 16, __nv_bfloat16, wmma::row_major> af[2];
                wmma::fragment<wmma::matrix_b, 16, 16, 16, __nv_bfloat16, wmma::col_major> bf[FN];
                #pragma unroll
                for (int i = 0; i < 2; ++i)
                    wmma::load_matrix_sync(af[i], &sA[(wr * 32 + i * 16) * LDA + kk * 16], LDA);
                #pragma unroll
                for (int j = 0; j < FN; ++j)
                    wmma::load_matrix_sync(bf[j], &sB[(wc * WN + j * 16) * LDB + kk * 16], LDB);
                #pragma unroll
                for (int i = 0; i < 2; ++i)
                    #pragma unroll
                    for (int j = 0; j < FN; ++j)
                        wmma::mma_sync(acc[i][j], af[i], bf[j], acc[i][j]);
            }
        }
    }

    // epilogue in 64-column halves, staged through fp32 smem
    #pragma unroll
    for (int hf = 0; hf < 2; ++hf) {
        __syncthreads();
        #pragma unroll
        for (int i = 0; i < 2; ++i)
            #pragma unroll
            for (int j = 0; j < FN; ++j) {
                int col = wc * WN + j * 16;
                if (col >= hf * 64 && col < (hf + 1) * 64)
                    wmma::store_matrix_sync(&stage[(wr * 32 + i * 16) * LDST + (col - hf * 64)],
                                            acc[i][j], LDST, wmma::mem_row_major);
            }
        __syncthreads();
        for (int i = tid; i < 128 * 64; i += 256) {
            int row = i >> 6, c = i & 63;
            int r = rowBase + row, col = hf * 64 + c;
            if (!fullTile && r >= N_NODES) continue;
            float a = stage[row * LDST + c];
            if (MODE == 0) {
                float v = fmaxf(a + bias[col], 0.f);
                int idx = r * H_DIM + col;
                g_h[idx] = v;
                float f0 = ALPHA * v;
                __nv_bfloat16 h = __float2bfloat16_rn(f0);
                g_f0h[idx] = h;
                g_f0l[idx] = __float2bfloat16_rn(f0 - __bfloat162float(h));
            } else {
                int idx = r * H_DIM + col;
                float v = fmaxf(a + bias[col] + g_h[idx], 0.f);
                g_h[idx] = v;
            }
        }
    }
}

// ======================= fc2: reads g_h fp32, converts to bf16 splits in-SMEM =======================
// acc = h@fc2_w (3 split passes per K-chunk from SMEM residency) -> out = acc + b
__global__ void __launch_bounds__(256) gemm_fc2(const float* __restrict__ bias,
                                                float* __restrict__ Cout) {
    constexpr int NDIM = 64;
    constexpr int KFULL = 128;
    constexpr int KC = 64;
    constexpr int LDA = 72, LDB = 72, LDST = 68;

    // Ah(128*72) + Al(128*72) + Bh(64*72) + Bl(64*72) bf16 = 55296 B; stage 128*68*4 = 34816 B
    __shared__ __align__(16) unsigned char smem[(2 * 128 + 2 * 64) * LDA * 2];
    __nv_bfloat16* sAh = (__nv_bfloat16*)smem;
    __nv_bfloat16* sAl = sAh + 128 * LDA;
    __nv_bfloat16* sBh = sAl + 128 * LDA;
    __nv_bfloat16* sBl = sBh + NDIM * LDB;
    float* stage = (float*)smem;

    const int tid = threadIdx.x;
    const int wid = tid >> 5;
    const int wr  = wid & 3;
    const int wc  = wid >> 2;
    const int rowBase = blockIdx.x * 128;
    const bool fullTile = (rowBase + 128 <= N_NODES);

    wmma::fragment<wmma::accumulator, 16, 16, 16, float> acc[2][2];
    #pragma unroll
    for (int i = 0; i < 2; ++i)
        #pragma unroll
        for (int j = 0; j < 2; ++j)
            wmma::fill_fragment(acc[i][j], 0.f);

    for (int kb = 0; kb < KFULL; kb += KC) {
        __syncthreads();
        // A: load fp32 h rows, split to bf16 hi/lo in SMEM (128 rows x 64 floats)
        #pragma unroll
        for (int i = tid; i < 128 * 16; i += 256) {
            int row = i >> 4, c4 = i & 15;
            float4 v = *(const float4*)(g_h + (size_t)(rowBase + row) * KFULL + kb + c4 * 4);
            __nv_bfloat16 b0 = __float2bfloat16_rn(v.x), b1 = __float2bfloat16_rn(v.y);
            __nv_bfloat16 b2 = __float2bfloat16_rn(v.z), b3 = __float2bfloat16_rn(v.w);
            __nv_bfloat16* ph = &sAh[row * LDA + c4 * 4];
            __nv_bfloat16* pl = &sAl[row * LDA + c4 * 4];
            ph[0] = b0; ph[1] = b1; ph[2] = b2; ph[3] = b3;
            pl[0] = __float2bfloat16_rn(v.x - __bfloat162float(b0));
            pl[1] = __float2bfloat16_rn(v.y - __bfloat162float(b1));
            pl[2] = __float2bfloat16_rn(v.z - __bfloat162float(b2));
            pl[3] = __float2bfloat16_rn(v.w - __bfloat162float(b3));
        }
        // B: hi and lo tiles (64 rows x 64 bf16 each)
        #pragma unroll
        for (int i = tid; i < NDIM * 8; i += 256) {
            int row = i >> 3, c8 = i & 7;
            size_t go = (size_t)row * KFULL + kb + c8 * 8;
            *(uint4*)&sBh[row * LDB + c8 * 8] = *(const uint4*)(g_w2Th + go);
            *(uint4*)&sBl[row * LDB + c8 * 8] = *(const uint4*)(g_w2Tl + go);
        }
        __syncthreads();
        #pragma unroll
        for (int pass = 0; pass < 3; ++pass) {
            const __nv_bfloat16* pA = (pass == 1) ? sAl : sAh;
            const __nv_bfloat16* pB = (pass == 2) ? sBl : sBh;
            #pragma unroll
            for (int kk = 0; kk < KC / 16; ++kk) {
                wmma::fragment<wmma::matrix_a, 16, 16, 16, __nv_bfloat16, wmma::row_major> af[2];
                wmma::fragment<wmma::matrix_b, 16, 16, 16, __nv_bfloat16, wmma::col_major> bf[2];
                #pragma unroll
                for (int i = 0; i < 2; ++i)
                    wmma::load_matrix_sync(af[i], &pA[(wr * 32 + i * 16) * LDA + kk * 16], LDA);
                #pragma unroll
                for (int j = 0; j < 2; ++j)
                    wmma::load_matrix_sync(bf[j], &pB[(wc * 32 + j * 16) * LDB + kk * 16], LDB);
                #pragma unroll
                for (int i = 0; i < 2; ++i)
                    #pragma unroll
                    for (int j = 0; j < 2; ++j)
                        wmma::mma_sync(acc[i][j], af[i], bf[j], acc[i][j]);
            }
        }
    }

    __syncthreads();
    #pragma unroll
    for (int i = 0; i < 2; ++i)
        #pragma unroll
        for (int j = 0; j < 2; ++j)
            wmma::store_matrix_sync(&stage[(wr * 32 + i * 16) * LDST + wc * 32 + j * 16],
                                    acc[i][j], LDST, wmma::mem_row_major);
    __syncthreads();
    for (int i = tid; i < 128 * 64; i += 256) {
        int row = i >> 6, c = i & 63;
        int r = rowBase + row;
        if (!fullTile && r >= N_NODES) continue;
        Cout[(size_t)r * C_DIM + c] = stage[row * LDST + c] + bias[c];
    }
}

// ======================= launch (R7 order) =======================
extern "C" void kernel_launch(void* const* d_in, const int* in_sizes, int n_in,
                              void* d_out, int out_size) {
    const float* x     = (const float*)d_in[0];
    const float* fc1_w = (const float*)d_in[1];
    const float* fc1_b = (const float*)d_in[2];
    const float* W1    = (const float*)d_in[3];
    const float* W2    = (const float*)d_in[4];
    const float* bgc   = (const float*)d_in[5];
    const float* fc2_w = (const float*)d_in[6];
    const float* fc2_b = (const float*)d_in[7];
    const int*   src   = (const int*)d_in[8];
    const int*   dst   = (const int*)d_in[9];
    float*       out   = (float*)d_out;

    const int TPB = 256;
    const int nodeBlocks = (N_NODES + TPB - 1) / TPB;
    const int edgeBlocks = (E_EDGES + TPB - 1) / TPB;
    const int prepBlocks = (N_NODES * IN_DIM / 4 + TPB - 1) / TPB;
    const int TILES = N_PAD / 128;   // 313

    init_kernel<<<nodeBlocks, TPB>>>();
    prep_kernel<<<prepBlocks, TPB>>>(src, dst, x, fc1_w, W1, W2, fc2_w);
    scan1_kernel<<<SCAN_NB, SCAN_B>>>();
    scan23_kernel<<<nodeBlocks, TPB>>>();
    fill_kernel<<<edgeBlocks, TPB>>>(src, dst);

    gemm_tc<0><<<TILES, 256>>>(fc1_b, 0);

    const int gatherBlocks = (N_NODES * 32 + TPB - 1) / TPB;
    for (int l = 0; l < L_LAYERS; ++l) {
        gather_kernel<<<gatherBlocks, TPB>>>();
        gemm_tc<1><<<TILES, 256>>>(bgc + (size_t)l * H_DIM, l);
    }

    gemm_fc2<<<TILES, 256>>>(fc2_b, out);
}

// round 12
// speedup vs baseline: 1.3914x; 1.0283x over previous
#include <cuda_runtime.h>
#include <cuda_bf16.h>
#include <mma.h>
#include <math.h>
#include <stdint.h>

using namespace nvcuda;

#define N_NODES 40000
#define N_PAD   40064          // 313 * 128
#define E_EDGES 640000
#define IN_DIM  256
#define H_DIM   128
#define C_DIM   64
#define L_LAYERS 4
#define ALPHA   0.5f
#define SCAN_B  1024
#define SCAN_NB 40

// ======================= device scratch (no allocations allowed) =======================
__device__ float g_h[N_PAD * H_DIM];                 // current features (fp32)
__device__ __nv_bfloat16 g_xh[N_PAD * IN_DIM], g_xl[N_PAD * IN_DIM];
__device__ __nv_bfloat16 g_f0h[N_PAD * H_DIM], g_f0l[N_PAD * H_DIM];
__device__ __nv_bfloat16 g_fth[N_PAD * H_DIM], g_ftl[N_PAD * H_DIM];
// transposed + split weights ([N][K], K contiguous). Layer weights: M = beta*W + (1-beta)*I.
__device__ __nv_bfloat16 g_w1Th[H_DIM * IN_DIM], g_w1Tl[H_DIM * IN_DIM];
__device__ __nv_bfloat16 g_WTh[L_LAYERS * 2 * H_DIM * H_DIM], g_WTl[L_LAYERS * 2 * H_DIM * H_DIM];
__device__ __nv_bfloat16 g_w2Th[C_DIM * H_DIM], g_w2Tl[C_DIM * H_DIM];
// CSR
__device__ float g_norm_s[N_NODES], g_norm_d[N_NODES];
__device__ int   g_cnt_in[N_NODES], g_cnt_out[N_NODES], g_fill[N_NODES];
__device__ int   g_rowptr[N_NODES + 1];
__device__ int   g_bsum[SCAN_NB];
__device__ int   g_csr_src[E_EDGES];
__device__ float g_csr_w[E_EDGES];

// ======================= kernel: init (counters + pad regions) =======================
__global__ void init_kernel() {
    int i = blockIdx.x * blockDim.x + threadIdx.x;
    const __nv_bfloat16 z = __float2bfloat16_rn(0.f);
    if (i < N_NODES) { g_cnt_in[i] = 0; g_cnt_out[i] = 0; }
    if (i < (N_PAD - N_NODES) * IN_DIM) {
        g_xh[N_NODES * IN_DIM + i] = z;
        g_xl[N_NODES * IN_DIM + i] = z;
    }
    if (i < (N_PAD - N_NODES) * H_DIM) {
        int o = N_NODES * H_DIM + i;
        g_f0h[o] = z; g_f0l[o] = z;
        g_fth[o] = z; g_ftl[o] = z;
        g_h[o] = 0.f;                     // fc2 reads g_h pad rows
    }
}

// ======================= prep: degree count + convert x + split weights =======================
__global__ void prep_kernel(const int* __restrict__ src, const int* __restrict__ dst,
                            const float* __restrict__ x,
                            const float* __restrict__ fc1_w,
                            const float* __restrict__ W1,
                            const float* __restrict__ W2,
                            const float* __restrict__ fc2_w) {
    int i = blockIdx.x * blockDim.x + threadIdx.x;
    if (i < E_EDGES) {
        atomicAdd(&g_cnt_in[dst[i]], 1);
        atomicAdd(&g_cnt_out[src[i]], 1);
    }
    if (i < N_NODES * IN_DIM / 4) {
        float4 v = ((const float4*)x)[i];
        __nv_bfloat16 b0 = __float2bfloat16_rn(v.x), b1 = __float2bfloat16_rn(v.y);
        __nv_bfloat16 b2 = __float2bfloat16_rn(v.z), b3 = __float2bfloat16_rn(v.w);
        __nv_bfloat162 h01; h01.x = b0; h01.y = b1;
        __nv_bfloat162 h23; h23.x = b2; h23.y = b3;
        __nv_bfloat162 l01; l01.x = __float2bfloat16_rn(v.x - __bfloat162float(b0));
                            l01.y = __float2bfloat16_rn(v.y - __bfloat162float(b1));
        __nv_bfloat162 l23; l23.x = __float2bfloat16_rn(v.z - __bfloat162float(b2));
                            l23.y = __float2bfloat16_rn(v.w - __bfloat162float(b3));
        size_t base = (size_t)i * 4;
        *(__nv_bfloat162*)(g_xh + base)     = h01;
        *(__nv_bfloat162*)(g_xh + base + 2) = h23;
        *(__nv_bfloat162*)(g_xl + base)     = l01;
        *(__nv_bfloat162*)(g_xl + base + 2) = l23;
    }
    if (i < H_DIM * IN_DIM) {
        int n = i / IN_DIM, k = i % IN_DIM;
        float w = fc1_w[k * H_DIM + n];
        __nv_bfloat16 h = __float2bfloat16_rn(w);
        g_w1Th[i] = h;
        g_w1Tl[i] = __float2bfloat16_rn(w - __bfloat162float(h));
    }
    if (i < L_LAYERS * 2 * H_DIM * H_DIM) {
        int l = i / (2 * H_DIM * H_DIM);
        int rem = i % (2 * H_DIM * H_DIM);
        int g = rem / (H_DIM * H_DIM);
        int nk = rem % (H_DIM * H_DIM);
        int n = nk / H_DIM, k = nk % H_DIM;
        float beta = logf(1.0f / (float)(l + 1) + 1.0f);
        const float* srcw = g ? W2 : W1;
        float w = beta * srcw[(size_t)l * H_DIM * H_DIM + k * H_DIM + n]
                + ((n == k) ? (1.0f - beta) : 0.0f);
        __nv_bfloat16 h = __float2bfloat16_rn(w);
        g_WTh[i] = h;
        g_WTl[i] = __float2bfloat16_rn(w - __bfloat162float(h));
    }
    if (i < C_DIM * H_DIM) {
        int n = i / H_DIM, k = i % H_DIM;
        float w = fc2_w[k * C_DIM + n];
        __nv_bfloat16 h = __float2bfloat16_rn(w);
        g_w2Th[i] = h;
        g_w2Tl[i] = __float2bfloat16_rn(w - __bfloat162float(h));
    }
}

// ======================= scan =======================
__global__ void scan1_kernel() {
    __shared__ int sh[SCAN_B];
    int tid = threadIdx.x;
    int gid = blockIdx.x * SCAN_B + tid;
    int v = (gid < N_NODES) ? g_cnt_in[gid] : 0;
    sh[tid] = v;
    __syncthreads();
    for (int off = 1; off < SCAN_B; off <<= 1) {
        int t = (tid >= off) ? sh[tid - off] : 0;
        __syncthreads();
        sh[tid] += t;
        __syncthreads();
    }
    if (gid < N_NODES) g_rowptr[gid] = sh[tid] - v;
    if (tid == SCAN_B - 1) g_bsum[blockIdx.x] = sh[tid];
}

__global__ void scan23_kernel() {
    __shared__ int sh[64];
    int tid = threadIdx.x;
    int v = (tid < SCAN_NB) ? g_bsum[tid] : 0;
    if (tid < 64) sh[tid] = v;
    __syncthreads();
    for (int off = 1; off < 64; off <<= 1) {
        int u = (tid < 64 && tid >= off) ? sh[tid - off] : 0;
        __syncthreads();
        if (tid < 64) sh[tid] += u;
        __syncthreads();
    }
    int gid = blockIdx.x * blockDim.x + tid;
    if (gid < N_NODES) {
        int b = gid >> 10;
        int rp = g_rowptr[gid] + sh[b] - g_bsum[b];
        g_rowptr[gid] = rp;
        g_fill[gid] = rp;
        g_norm_s[gid] = rsqrtf(fmaxf((float)g_cnt_out[gid], 1.f));
        g_norm_d[gid] = rsqrtf(fmaxf((float)g_cnt_in[gid], 1.f));
    }
    if (gid == 0) g_rowptr[N_NODES] = E_EDGES;
}

__global__ void fill_kernel(const int* __restrict__ src, const int* __restrict__ dst) {
    int e = blockIdx.x * blockDim.x + threadIdx.x;
    if (e < E_EDGES) {
        int d = dst[e], s = src[e];
        int pos = atomicAdd(&g_fill[d], 1);
        g_csr_src[pos] = s;
        g_csr_w[pos] = g_norm_s[s];
    }
}

// ---------------- gather SpMM: one warp per dst row; 8-wide unrolled sub-chunks ----------------
__global__ void gather_kernel() {
    int gw = (blockIdx.x * blockDim.x + threadIdx.x) >> 5;
    int lane = threadIdx.x & 31;
    if (gw >= N_NODES) return;
    int beg = g_rowptr[gw];
    int end = g_rowptr[gw + 1];
    float4 acc = make_float4(0.f, 0.f, 0.f, 0.f);
    for (int base = beg; base < end; base += 32) {
        int e = base + lane;
        int s = 0; float wgt = 0.f;
        if (e < end) { s = g_csr_src[e]; wgt = g_csr_w[e]; }
        #pragma unroll
        for (int c = 0; c < 4; ++c) {
            if (base + c * 8 >= end) break;   // warp-uniform
            #pragma unroll
            for (int j = 0; j < 8; ++j) {
                int jj = c * 8 + j;
                int   sj = __shfl_sync(0xffffffffu, s, jj);
                float wj = __shfl_sync(0xffffffffu, wgt, jj);
                float4 v = __ldg((const float4*)(g_h + (size_t)sj * H_DIM) + lane);
                acc.x += v.x * wj; acc.y += v.y * wj;
                acc.z += v.z * wj; acc.w += v.w * wj;
            }
        }
    }
    float sc = (1.f - ALPHA) * g_norm_d[gw];
    float f0 = acc.x * sc, f1 = acc.y * sc, f2 = acc.z * sc, f3 = acc.w * sc;
    __nv_bfloat16 b0 = __float2bfloat16_rn(f0), b1 = __float2bfloat16_rn(f1);
    __nv_bfloat16 b2 = __float2bfloat16_rn(f2), b3 = __float2bfloat16_rn(f3);
    size_t base = (size_t)gw * H_DIM + lane * 4;
    __nv_bfloat162 h01; h01.x = b0; h01.y = b1;
    __nv_bfloat162 h23; h23.x = b2; h23.y = b3;
    *(__nv_bfloat162*)(g_fth + base)     = h01;
    *(__nv_bfloat162*)(g_fth + base + 2) = h23;
    __nv_bfloat162 l01; l01.x = __float2bfloat16_rn(f0 - __bfloat162float(b0));
                        l01.y = __float2bfloat16_rn(f1 - __bfloat162float(b1));
    __nv_bfloat162 l23; l23.x = __float2bfloat16_rn(f2 - __bfloat162float(b2));
                        l23.y = __float2bfloat16_rn(f3 - __bfloat162float(b3));
    *(__nv_bfloat162*)(g_ftl + base)     = l01;
    *(__nv_bfloat162*)(g_ftl + base + 2) = l23;
}

// ======================= WMMA bf16-split GEMM (R7 structure; 2 CTAs/SM) =======================
// MODE 0: acc = x@fc1_w  -> h = relu(acc+b); f0 = split(ALPHA*h)
// MODE 1: acc = feat@M1 + f0@M2 -> h = relu(acc + bgc + h)
template <int MODE>
__global__ void __launch_bounds__(256, 2) gemm_tc(const float* __restrict__ bias,
                                                  int layer) {
    constexpr int NDIM  = 128;
    constexpr int KFULL = (MODE == 0) ? 256 : 128;
    constexpr int NPROD = (MODE == 1) ? 6 : 3;
    constexpr int KC = 64;
    constexpr int LDA = 72, LDB = 72, LDST = 68;
    constexpr int WN = NDIM / 2;
    constexpr int FN = WN / 16;

    __shared__ __align__(16) unsigned char smem[128 * LDA * 2 + 128 * LDB * 2];
    __nv_bfloat16* sA = (__nv_bfloat16*)smem;
    __nv_bfloat16* sB = sA + 128 * LDA;
    float* stage = (float*)smem;

    const int tid = threadIdx.x;
    const int wid = tid >> 5;
    const int wr  = wid & 3;
    const int wc  = wid >> 2;
    const int rowBase = blockIdx.x * 128;
    const bool fullTile = (rowBase + 128 <= N_NODES);

    wmma::fragment<wmma::accumulator, 16, 16, 16, float> acc[2][FN];
    #pragma unroll
    for (int i = 0; i < 2; ++i)
        #pragma unroll
        for (int j = 0; j < FN; ++j)
            wmma::fill_fragment(acc[i][j], 0.f);

    for (int prod = 0; prod < NPROD; ++prod) {
        const __nv_bfloat16 *Ap, *Bp;
        if (MODE == 0) {
            Ap = (prod == 1) ? g_xl : g_xh;
            Bp = (prod == 2) ? g_w1Tl : g_w1Th;
        } else {
            int g = prod / 3, q = prod % 3;
            Ap = g ? ((q == 1) ? g_f0l : g_f0h) : ((q == 1) ? g_ftl : g_fth);
            size_t wo = (size_t)(layer * 2 + g) * H_DIM * H_DIM;
            Bp = (q == 2) ? (g_WTl + wo) : (g_WTh + wo);
        }
        for (int kb = 0; kb < KFULL; kb += KC) {
            __syncthreads();
            #pragma unroll
            for (int i = tid; i < 128 * 8; i += 256) {
                int row = i >> 3, c8 = i & 7;
                *(uint4*)&sA[row * LDA + c8 * 8] =
                    *(const uint4*)(Ap + (size_t)(rowBase + row) * KFULL + kb + c8 * 8);
            }
            #pragma unroll
            for (int i = tid; i < NDIM * 8; i += 256) {
                int row = i >> 3, c8 = i & 7;
                *(uint4*)&sB[row * LDB + c8 * 8] =
                    *(const uint4*)(Bp + (size_t)row * KFULL + kb + c8 * 8);
            }
            __syncthreads();
            #pragma unroll
            for (int kk = 0; kk < KC / 16; ++kk) {
                wmma::fragment<wmma::matrix_a, 16, 16, 16, __nv_bfloat16, wmma::row_major> af[2];
                wmma::fragment<wmma::matrix_b, 16, 16, 16, __nv_bfloat16, wmma::col_major> bf[FN];
                #pragma unroll
                for (int i = 0; i < 2; ++i)
                    wmma::load_matrix_sync(af[i], &sA[(wr * 32 + i * 16) * LDA + kk * 16], LDA);
                #pragma unroll
                for (int j = 0; j < FN; ++j)
                    wmma::load_matrix_sync(bf[j], &sB[(wc * WN + j * 16) * LDB + kk * 16], LDB);
                #pragma unroll
                for (int i = 0; i < 2; ++i)
                    #pragma unroll
                    for (int j = 0; j < FN; ++j)
                        wmma::mma_sync(acc[i][j], af[i], bf[j], acc[i][j]);
            }
        }
    }

    // epilogue in 64-column halves, staged through fp32 smem
    #pragma unroll
    for (int hf = 0; hf < 2; ++hf) {
        __syncthreads();
        #pragma unroll
        for (int i = 0; i < 2; ++i)
            #pragma unroll
            for (int j = 0; j < FN; ++j) {
                int col = wc * WN + j * 16;
                if (col >= hf * 64 && col < (hf + 1) * 64)
                    wmma::store_matrix_sync(&stage[(wr * 32 + i * 16) * LDST + (col - hf * 64)],
                                            acc[i][j], LDST, wmma::mem_row_major);
            }
        __syncthreads();
        for (int i = tid; i < 128 * 64; i += 256) {
            int row = i >> 6, c = i & 63;
            int r = rowBase + row, col = hf * 64 + c;
            if (!fullTile && r >= N_NODES) continue;
            float a = stage[row * LDST + c];
            if (MODE == 0) {
                float v = fmaxf(a + bias[col], 0.f);
                int idx = r * H_DIM + col;
                g_h[idx] = v;
                float f0 = ALPHA * v;
                __nv_bfloat16 h = __float2bfloat16_rn(f0);
                g_f0h[idx] = h;
                g_f0l[idx] = __float2bfloat16_rn(f0 - __bfloat162float(h));
            } else {
                int idx = r * H_DIM + col;
                float v = fmaxf(a + bias[col] + g_h[idx], 0.f);
                g_h[idx] = v;
            }
        }
    }
}

// ======================= fc2: reads g_h fp32, converts to bf16 splits in-SMEM =======================
// acc = h@fc2_w (3 split passes per K-chunk from SMEM residency) -> out = acc + b
__global__ void __launch_bounds__(256, 2) gemm_fc2(const float* __restrict__ bias,
                                                   float* __restrict__ Cout) {
    constexpr int NDIM = 64;
    constexpr int KFULL = 128;
    constexpr int KC = 64;
    constexpr int LDA = 72, LDB = 72, LDST = 68;

    // Ah(128*72) + Al(128*72) + Bh(64*72) + Bl(64*72) bf16 = 55296 B; stage 128*68*4 = 34816 B
    __shared__ __align__(16) unsigned char smem[(2 * 128 + 2 * 64) * LDA * 2];
    __nv_bfloat16* sAh = (__nv_bfloat16*)smem;
    __nv_bfloat16* sAl = sAh + 128 * LDA;
    __nv_bfloat16* sBh = sAl + 128 * LDA;
    __nv_bfloat16* sBl = sBh + NDIM * LDB;
    float* stage = (float*)smem;

    const int tid = threadIdx.x;
    const int wid = tid >> 5;
    const int wr  = wid & 3;
    const int wc  = wid >> 2;
    const int rowBase = blockIdx.x * 128;
    const bool fullTile = (rowBase + 128 <= N_NODES);

    wmma::fragment<wmma::accumulator, 16, 16, 16, float> acc[2][2];
    #pragma unroll
    for (int i = 0; i < 2; ++i)
        #pragma unroll
        for (int j = 0; j < 2; ++j)
            wmma::fill_fragment(acc[i][j], 0.f);

    for (int kb = 0; kb < KFULL; kb += KC) {
        __syncthreads();
        // A: load fp32 h rows, split to bf16 hi/lo in SMEM (128 rows x 64 floats)
        #pragma unroll
        for (int i = tid; i < 128 * 16; i += 256) {
            int row = i >> 4, c4 = i & 15;
            float4 v = *(const float4*)(g_h + (size_t)(rowBase + row) * KFULL + kb + c4 * 4);
            __nv_bfloat16 b0 = __float2bfloat16_rn(v.x), b1 = __float2bfloat16_rn(v.y);
            __nv_bfloat16 b2 = __float2bfloat16_rn(v.z), b3 = __float2bfloat16_rn(v.w);
            __nv_bfloat16* ph = &sAh[row * LDA + c4 * 4];
            __nv_bfloat16* pl = &sAl[row * LDA + c4 * 4];
            ph[0] = b0; ph[1] = b1; ph[2] = b2; ph[3] = b3;
            pl[0] = __float2bfloat16_rn(v.x - __bfloat162float(b0));
            pl[1] = __float2bfloat16_rn(v.y - __bfloat162float(b1));
            pl[2] = __float2bfloat16_rn(v.z - __bfloat162float(b2));
            pl[3] = __float2bfloat16_rn(v.w - __bfloat162float(b3));
        }
        // B: hi and lo tiles (64 rows x 64 bf16 each)
        #pragma unroll
        for (int i = tid; i < NDIM * 8; i += 256) {
            int row = i >> 3, c8 = i & 7;
            size_t go = (size_t)row * KFULL + kb + c8 * 8;
            *(uint4*)&sBh[row * LDB + c8 * 8] = *(const uint4*)(g_w2Th + go);
            *(uint4*)&sBl[row * LDB + c8 * 8] = *(const uint4*)(g_w2Tl + go);
        }
        __syncthreads();
        #pragma unroll
        for (int pass = 0; pass < 3; ++pass) {
            const __nv_bfloat16* pA = (pass == 1) ? sAl : sAh;
            const __nv_bfloat16* pB = (pass == 2) ? sBl : sBh;
            #pragma unroll
            for (int kk = 0; kk < KC / 16; ++kk) {
                wmma::fragment<wmma::matrix_a, 16, 16, 16, __nv_bfloat16, wmma::row_major> af[2];
                wmma::fragment<wmma::matrix_b, 16, 16, 16, __nv_bfloat16, wmma::col_major> bf[2];
                #pragma unroll
                for (int i = 0; i < 2; ++i)
                    wmma::load_matrix_sync(af[i], &pA[(wr * 32 + i * 16) * LDA + kk * 16], LDA);
                #pragma unroll
                for (int j = 0; j < 2; ++j)
                    wmma::load_matrix_sync(bf[j], &pB[(wc * 32 + j * 16) * LDB + kk * 16], LDB);
                #pragma unroll
                for (int i = 0; i < 2; ++i)
                    #pragma unroll
                    for (int j = 0; j < 2; ++j)
                        wmma::mma_sync(acc[i][j], af[i], bf[j], acc[i][j]);
            }
        }
    }

    __syncthreads();
    #pragma unroll
    for (int i = 0; i < 2; ++i)
        #pragma unroll
        for (int j = 0; j < 2; ++j)
            wmma::store_matrix_sync(&stage[(wr * 32 + i * 16) * LDST + wc * 32 + j * 16],
                                    acc[i][j], LDST, wmma::mem_row_major);
    __syncthreads();
    for (int i = tid; i < 128 * 64; i += 256) {
        int row = i >> 6, c = i & 63;
        int r = rowBase + row;
        if (!fullTile && r >= N_NODES) continue;
        Cout[(size_t)r * C_DIM + c] = stage[row * LDST + c] + bias[c];
    }
}

// ======================= launch (R7 order) =======================
extern "C" void kernel_launch(void* const* d_in, const int* in_sizes, int n_in,
                              void* d_out, int out_size) {
    const float* x     = (const float*)d_in[0];
    const float* fc1_w = (const float*)d_in[1];
    const float* fc1_b = (const float*)d_in[2];
    const float* W1    = (const float*)d_in[3];
    const float* W2    = (const float*)d_in[4];
    const float* bgc   = (const float*)d_in[5];
    const float* fc2_w = (const float*)d_in[6];
    const float* fc2_b = (const float*)d_in[7];
    const int*   src   = (const int*)d_in[8];
    const int*   dst   = (const int*)d_in[9];
    float*       out   = (float*)d_out;

    const int TPB = 256;
    const int nodeBlocks = (N_NODES + TPB - 1) / TPB;
    const int edgeBlocks = (E_EDGES + TPB - 1) / TPB;
    const int prepBlocks = (N_NODES * IN_DIM / 4 + TPB - 1) / TPB;
    const int TILES = N_PAD / 128;   // 313

    init_kernel<<<nodeBlocks, TPB>>>();
    prep_kernel<<<prepBlocks, TPB>>>(src, dst, x, fc1_w, W1, W2, fc2_w);
    scan1_kernel<<<SCAN_NB, SCAN_B>>>();
    scan23_kernel<<<nodeBlocks, TPB>>>();
    fill_kernel<<<edgeBlocks, TPB>>>(src, dst);

    gemm_tc<0><<<TILES, 256>>>(fc1_b, 0);

    const int gatherBlocks = (N_NODES * 32 + TPB - 1) / TPB;
    for (int l = 0; l < L_LAYERS; ++l) {
        gather_kernel<<<gatherBlocks, TPB>>>();
        gemm_tc<1><<<TILES, 256>>>(bgc + (size_t)l * H_DIM, l);
    }

    gemm_fc2<<<TILES, 256>>>(fc2_b, out);
}

// round 13
// speedup vs baseline: 1.4338x; 1.0304x over previous
#include <cuda_runtime.h>
#include <cuda_bf16.h>
#include <mma.h>
#include <math.h>
#include <stdint.h>

using namespace nvcuda;

#define N_NODES 40000
#define N_PAD   40064          // 313 * 128
#define E_EDGES 640000
#define IN_DIM  256
#define H_DIM   128
#define C_DIM   64
#define L_LAYERS 4
#define ALPHA   0.5f
#define SCAN_B  1024
#define SCAN_NB 40

// ======================= device scratch (no allocations allowed) =======================
__device__ float g_h[N_PAD * H_DIM];                 // current features (fp32)
__device__ __nv_bfloat16 g_xh[N_PAD * IN_DIM], g_xl[N_PAD * IN_DIM];
__device__ __nv_bfloat16 g_f0h[N_PAD * H_DIM], g_f0l[N_PAD * H_DIM];
__device__ __nv_bfloat16 g_fth[N_PAD * H_DIM], g_ftl[N_PAD * H_DIM];
// transposed + split weights ([N][K], K contiguous). Layer weights: M = beta*W + (1-beta)*I.
__device__ __nv_bfloat16 g_w1Th[H_DIM * IN_DIM], g_w1Tl[H_DIM * IN_DIM];
__device__ __nv_bfloat16 g_WTh[L_LAYERS * 2 * H_DIM * H_DIM], g_WTl[L_LAYERS * 2 * H_DIM * H_DIM];
__device__ __nv_bfloat16 g_w2Th[C_DIM * H_DIM], g_w2Tl[C_DIM * H_DIM];
// CSR
__device__ float g_norm_s[N_NODES], g_norm_d[N_NODES];
__device__ int   g_cnt_in[N_NODES], g_cnt_out[N_NODES], g_fill[N_NODES];
__device__ int   g_rowptr[N_NODES + 1];
__device__ int   g_bsum[SCAN_NB];
__device__ int   g_csr_src[E_EDGES];
__device__ float g_csr_w[E_EDGES];

// ======================= init (counters + pad regions) =======================
__global__ void init_kernel() {
    int i = blockIdx.x * blockDim.x + threadIdx.x;
    const __nv_bfloat16 z = __float2bfloat16_rn(0.f);
    if (i < N_NODES) { g_cnt_in[i] = 0; g_cnt_out[i] = 0; }
    if (i < (N_PAD - N_NODES) * IN_DIM) {
        g_xh[N_NODES * IN_DIM + i] = z;
        g_xl[N_NODES * IN_DIM + i] = z;
    }
    if (i < (N_PAD - N_NODES) * H_DIM) {
        int o = N_NODES * H_DIM + i;
        g_f0h[o] = z; g_f0l[o] = z;
        g_fth[o] = z; g_ftl[o] = z;
        g_h[o] = 0.f;                     // fc2 reads g_h pad rows
    }
}

// ======================= chain B: edge degree count =======================
__global__ void prep_edges_kernel(const int* __restrict__ src, const int* __restrict__ dst) {
    int i = blockIdx.x * blockDim.x + threadIdx.x;
    if (i < E_EDGES) {
        atomicAdd(&g_cnt_in[dst[i]], 1);
        atomicAdd(&g_cnt_out[src[i]], 1);
    }
}

// ======================= chain A: convert x + split weights =======================
__global__ void prep_convert_kernel(const float* __restrict__ x,
                                    const float* __restrict__ fc1_w,
                                    const float* __restrict__ W1,
                                    const float* __restrict__ W2,
                                    const float* __restrict__ fc2_w) {
    int i = blockIdx.x * blockDim.x + threadIdx.x;
    if (i < N_NODES * IN_DIM / 4) {
        float4 v = ((const float4*)x)[i];
        __nv_bfloat16 b0 = __float2bfloat16_rn(v.x), b1 = __float2bfloat16_rn(v.y);
        __nv_bfloat16 b2 = __float2bfloat16_rn(v.z), b3 = __float2bfloat16_rn(v.w);
        __nv_bfloat162 h01; h01.x = b0; h01.y = b1;
        __nv_bfloat162 h23; h23.x = b2; h23.y = b3;
        __nv_bfloat162 l01; l01.x = __float2bfloat16_rn(v.x - __bfloat162float(b0));
                            l01.y = __float2bfloat16_rn(v.y - __bfloat162float(b1));
        __nv_bfloat162 l23; l23.x = __float2bfloat16_rn(v.z - __bfloat162float(b2));
                            l23.y = __float2bfloat16_rn(v.w - __bfloat162float(b3));
        size_t base = (size_t)i * 4;
        *(__nv_bfloat162*)(g_xh + base)     = h01;
        *(__nv_bfloat162*)(g_xh + base + 2) = h23;
        *(__nv_bfloat162*)(g_xl + base)     = l01;
        *(__nv_bfloat162*)(g_xl + base + 2) = l23;
    }
    if (i < H_DIM * IN_DIM) {
        int n = i / IN_DIM, k = i % IN_DIM;
        float w = fc1_w[k * H_DIM + n];
        __nv_bfloat16 h = __float2bfloat16_rn(w);
        g_w1Th[i] = h;
        g_w1Tl[i] = __float2bfloat16_rn(w - __bfloat162float(h));
    }
    if (i < L_LAYERS * 2 * H_DIM * H_DIM) {
        int l = i / (2 * H_DIM * H_DIM);
        int rem = i % (2 * H_DIM * H_DIM);
        int g = rem / (H_DIM * H_DIM);
        int nk = rem % (H_DIM * H_DIM);
        int n = nk / H_DIM, k = nk % H_DIM;
        float beta = logf(1.0f / (float)(l + 1) + 1.0f);
        const float* srcw = g ? W2 : W1;
        float w = beta * srcw[(size_t)l * H_DIM * H_DIM + k * H_DIM + n]
                + ((n == k) ? (1.0f - beta) : 0.0f);
        __nv_bfloat16 h = __float2bfloat16_rn(w);
        g_WTh[i] = h;
        g_WTl[i] = __float2bfloat16_rn(w - __bfloat162float(h));
    }
    if (i < C_DIM * H_DIM) {
        int n = i / H_DIM, k = i % H_DIM;
        float w = fc2_w[k * C_DIM + n];
        __nv_bfloat16 h = __float2bfloat16_rn(w);
        g_w2Th[i] = h;
        g_w2Tl[i] = __float2bfloat16_rn(w - __bfloat162float(h));
    }
}

// ======================= scan =======================
__global__ void scan1_kernel() {
    __shared__ int sh[SCAN_B];
    int tid = threadIdx.x;
    int gid = blockIdx.x * SCAN_B + tid;
    int v = (gid < N_NODES) ? g_cnt_in[gid] : 0;
    sh[tid] = v;
    __syncthreads();
    for (int off = 1; off < SCAN_B; off <<= 1) {
        int t = (tid >= off) ? sh[tid - off] : 0;
        __syncthreads();
        sh[tid] += t;
        __syncthreads();
    }
    if (gid < N_NODES) g_rowptr[gid] = sh[tid] - v;
    if (tid == SCAN_B - 1) g_bsum[blockIdx.x] = sh[tid];
}

__global__ void scan23_kernel() {
    __shared__ int sh[64];
    int tid = threadIdx.x;
    int v = (tid < SCAN_NB) ? g_bsum[tid] : 0;
    if (tid < 64) sh[tid] = v;
    __syncthreads();
    for (int off = 1; off < 64; off <<= 1) {
        int u = (tid < 64 && tid >= off) ? sh[tid - off] : 0;
        __syncthreads();
        if (tid < 64) sh[tid] += u;
        __syncthreads();
    }
    int gid = blockIdx.x * blockDim.x + tid;
    if (gid < N_NODES) {
        int b = gid >> 10;
        int rp = g_rowptr[gid] + sh[b] - g_bsum[b];
        g_rowptr[gid] = rp;
        g_fill[gid] = rp;
        g_norm_s[gid] = rsqrtf(fmaxf((float)g_cnt_out[gid], 1.f));
        g_norm_d[gid] = rsqrtf(fmaxf((float)g_cnt_in[gid], 1.f));
    }
    if (gid == 0) g_rowptr[N_NODES] = E_EDGES;
}

__global__ void fill_kernel(const int* __restrict__ src, const int* __restrict__ dst) {
    int e = blockIdx.x * blockDim.x + threadIdx.x;
    if (e < E_EDGES) {
        int d = dst[e], s = src[e];
        int pos = atomicAdd(&g_fill[d], 1);
        g_csr_src[pos] = s;
        g_csr_w[pos] = g_norm_s[s];
    }
}

// ---------------- gather SpMM: one warp per dst row; 8-wide unrolled sub-chunks ----------------
__global__ void gather_kernel() {
    int gw = (blockIdx.x * blockDim.x + threadIdx.x) >> 5;
    int lane = threadIdx.x & 31;
    if (gw >= N_NODES) return;
    int beg = g_rowptr[gw];
    int end = g_rowptr[gw + 1];
    float4 acc = make_float4(0.f, 0.f, 0.f, 0.f);
    for (int base = beg; base < end; base += 32) {
        int e = base + lane;
        int s = 0; float wgt = 0.f;
        if (e < end) { s = g_csr_src[e]; wgt = g_csr_w[e]; }
        #pragma unroll
        for (int c = 0; c < 4; ++c) {
            if (base + c * 8 >= end) break;   // warp-uniform
            #pragma unroll
            for (int j = 0; j < 8; ++j) {
                int jj = c * 8 + j;
                int   sj = __shfl_sync(0xffffffffu, s, jj);
                float wj = __shfl_sync(0xffffffffu, wgt, jj);
                float4 v = __ldg((const float4*)(g_h + (size_t)sj * H_DIM) + lane);
                acc.x += v.x * wj; acc.y += v.y * wj;
                acc.z += v.z * wj; acc.w += v.w * wj;
            }
        }
    }
    float sc = (1.f - ALPHA) * g_norm_d[gw];
    float f0 = acc.x * sc, f1 = acc.y * sc, f2 = acc.z * sc, f3 = acc.w * sc;
    __nv_bfloat16 b0 = __float2bfloat16_rn(f0), b1 = __float2bfloat16_rn(f1);
    __nv_bfloat16 b2 = __float2bfloat16_rn(f2), b3 = __float2bfloat16_rn(f3);
    size_t base = (size_t)gw * H_DIM + lane * 4;
    __nv_bfloat162 h01; h01.x = b0; h01.y = b1;
    __nv_bfloat162 h23; h23.x = b2; h23.y = b3;
    *(__nv_bfloat162*)(g_fth + base)     = h01;
    *(__nv_bfloat162*)(g_fth + base + 2) = h23;
    __nv_bfloat162 l01; l01.x = __float2bfloat16_rn(f0 - __bfloat162float(b0));
                        l01.y = __float2bfloat16_rn(f1 - __bfloat162float(b1));
    __nv_bfloat162 l23; l23.x = __float2bfloat16_rn(f2 - __bfloat162float(b2));
                        l23.y = __float2bfloat16_rn(f3 - __bfloat162float(b3));
    *(__nv_bfloat162*)(g_ftl + base)     = l01;
    *(__nv_bfloat162*)(g_ftl + base + 2) = l23;
}

// ======================= WMMA bf16-split GEMM (2 CTAs/SM) =======================
// MODE 0: acc = x@fc1_w  -> h = relu(acc+b); f0 = split(ALPHA*h)
// MODE 1: acc = feat@M1 + f0@M2 -> h = relu(acc + bgc + h)
template <int MODE>
__global__ void __launch_bounds__(256, 2) gemm_tc(const float* __restrict__ bias,
                                                  int layer) {
    constexpr int NDIM  = 128;
    constexpr int KFULL = (MODE == 0) ? 256 : 128;
    constexpr int NPROD = (MODE == 1) ? 6 : 3;
    constexpr int KC = 64;
    constexpr int LDA = 72, LDB = 72, LDST = 68;
    constexpr int WN = NDIM / 2;
    constexpr int FN = WN / 16;

    __shared__ __align__(16) unsigned char smem[128 * LDA * 2 + 128 * LDB * 2];
    __nv_bfloat16* sA = (__nv_bfloat16*)smem;
    __nv_bfloat16* sB = sA + 128 * LDA;
    float* stage = (float*)smem;

    const int tid = threadIdx.x;
    const int wid = tid >> 5;
    const int wr  = wid & 3;
    const int wc  = wid >> 2;
    const int rowBase = blockIdx.x * 128;
    const bool fullTile = (rowBase + 128 <= N_NODES);

    wmma::fragment<wmma::accumulator, 16, 16, 16, float> acc[2][FN];
    #pragma unroll
    for (int i = 0; i < 2; ++i)
        #pragma unroll
        for (int j = 0; j < FN; ++j)
            wmma::fill_fragment(acc[i][j], 0.f);

    for (int prod = 0; prod < NPROD; ++prod) {
        const __nv_bfloat16 *Ap, *Bp;
        if (MODE == 0) {
            Ap = (prod == 1) ? g_xl : g_xh;
            Bp = (prod == 2) ? g_w1Tl : g_w1Th;
        } else {
            int g = prod / 3, q = prod % 3;
            Ap = g ? ((q == 1) ? g_f0l : g_f0h) : ((q == 1) ? g_ftl : g_fth);
            size_t wo = (size_t)(layer * 2 + g) * H_DIM * H_DIM;
            Bp = (q == 2) ? (g_WTl + wo) : (g_WTh + wo);
        }
        for (int kb = 0; kb < KFULL; kb += KC) {
            __syncthreads();
            #pragma unroll
            for (int i = tid; i < 128 * 8; i += 256) {
                int row = i >> 3, c8 = i & 7;
                *(uint4*)&sA[row * LDA + c8 * 8] =
                    *(const uint4*)(Ap + (size_t)(rowBase + row) * KFULL + kb + c8 * 8);
            }
            #pragma unroll
            for (int i = tid; i < NDIM * 8; i += 256) {
                int row = i >> 3, c8 = i & 7;
                *(uint4*)&sB[row * LDB + c8 * 8] =
                    *(const uint4*)(Bp + (size_t)row * KFULL + kb + c8 * 8);
            }
            __syncthreads();
            #pragma unroll
            for (int kk = 0; kk < KC / 16; ++kk) {
                wmma::fragment<wmma::matrix_a, 16, 16, 16, __nv_bfloat16, wmma::row_major> af[2];
                wmma::fragment<wmma::matrix_b, 16, 16, 16, __nv_bfloat16, wmma::col_major> bf[FN];
                #pragma unroll
                for (int i = 0; i < 2; ++i)
                    wmma::load_matrix_sync(af[i], &sA[(wr * 32 + i * 16) * LDA + kk * 16], LDA);
                #pragma unroll
                for (int j = 0; j < FN; ++j)
                    wmma::load_matrix_sync(bf[j], &sB[(wc * WN + j * 16) * LDB + kk * 16], LDB);
                #pragma unroll
                for (int i = 0; i < 2; ++i)
                    #pragma unroll
                    for (int j = 0; j < FN; ++j)
                        wmma::mma_sync(acc[i][j], af[i], bf[j], acc[i][j]);
            }
        }
    }

    // epilogue in 64-column halves, staged through fp32 smem
    #pragma unroll
    for (int hf = 0; hf < 2; ++hf) {
        __syncthreads();
        #pragma unroll
        for (int i = 0; i < 2; ++i)
            #pragma unroll
            for (int j = 0; j < FN; ++j) {
                int col = wc * WN + j * 16;
                if (col >= hf * 64 && col < (hf + 1) * 64)
                    wmma::store_matrix_sync(&stage[(wr * 32 + i * 16) * LDST + (col - hf * 64)],
                                            acc[i][j], LDST, wmma::mem_row_major);
            }
        __syncthreads();
        for (int i = tid; i < 128 * 64; i += 256) {
            int row = i >> 6, c = i & 63;
            int r = rowBase + row, col = hf * 64 + c;
            if (!fullTile && r >= N_NODES) continue;
            float a = stage[row * LDST + c];
            if (MODE == 0) {
                float v = fmaxf(a + bias[col], 0.f);
                int idx = r * H_DIM + col;
                g_h[idx] = v;
                float f0 = ALPHA * v;
                __nv_bfloat16 h = __float2bfloat16_rn(f0);
                g_f0h[idx] = h;
                g_f0l[idx] = __float2bfloat16_rn(f0 - __bfloat162float(h));
            } else {
                int idx = r * H_DIM + col;
                float v = fmaxf(a + bias[col] + g_h[idx], 0.f);
                g_h[idx] = v;
            }
        }
    }
}

// ======================= fc2: reads g_h fp32, converts to bf16 splits in-SMEM =======================
__global__ void __launch_bounds__(256, 2) gemm_fc2(const float* __restrict__ bias,
                                                   float* __restrict__ Cout) {
    constexpr int NDIM = 64;
    constexpr int KFULL = 128;
    constexpr int KC = 64;
    constexpr int LDA = 72, LDB = 72, LDST = 68;

    __shared__ __align__(16) unsigned char smem[(2 * 128 + 2 * 64) * LDA * 2];
    __nv_bfloat16* sAh = (__nv_bfloat16*)smem;
    __nv_bfloat16* sAl = sAh + 128 * LDA;
    __nv_bfloat16* sBh = sAl + 128 * LDA;
    __nv_bfloat16* sBl = sBh + NDIM * LDB;
    float* stage = (float*)smem;

    const int tid = threadIdx.x;
    const int wid = tid >> 5;
    const int wr  = wid & 3;
    const int wc  = wid >> 2;
    const int rowBase = blockIdx.x * 128;
    const bool fullTile = (rowBase + 128 <= N_NODES);

    wmma::fragment<wmma::accumulator, 16, 16, 16, float> acc[2][2];
    #pragma unroll
    for (int i = 0; i < 2; ++i)
        #pragma unroll
        for (int j = 0; j < 2; ++j)
            wmma::fill_fragment(acc[i][j], 0.f);

    for (int kb = 0; kb < KFULL; kb += KC) {
        __syncthreads();
        #pragma unroll
        for (int i = tid; i < 128 * 16; i += 256) {
            int row = i >> 4, c4 = i & 15;
            float4 v = *(const float4*)(g_h + (size_t)(rowBase + row) * KFULL + kb + c4 * 4);
            __nv_bfloat16 b0 = __float2bfloat16_rn(v.x), b1 = __float2bfloat16_rn(v.y);
            __nv_bfloat16 b2 = __float2bfloat16_rn(v.z), b3 = __float2bfloat16_rn(v.w);
            __nv_bfloat16* ph = &sAh[row * LDA + c4 * 4];
            __nv_bfloat16* pl = &sAl[row * LDA + c4 * 4];
            ph[0] = b0; ph[1] = b1; ph[2] = b2; ph[3] = b3;
            pl[0] = __float2bfloat16_rn(v.x - __bfloat162float(b0));
            pl[1] = __float2bfloat16_rn(v.y - __bfloat162float(b1));
            pl[2] = __float2bfloat16_rn(v.z - __bfloat162float(b2));
            pl[3] = __float2bfloat16_rn(v.w - __bfloat162float(b3));
        }
        #pragma unroll
        for (int i = tid; i < NDIM * 8; i += 256) {
            int row = i >> 3, c8 = i & 7;
            size_t go = (size_t)row * KFULL + kb + c8 * 8;
            *(uint4*)&sBh[row * LDB + c8 * 8] = *(const uint4*)(g_w2Th + go);
            *(uint4*)&sBl[row * LDB + c8 * 8] = *(const uint4*)(g_w2Tl + go);
        }
        __syncthreads();
        #pragma unroll
        for (int pass = 0; pass < 3; ++pass) {
            const __nv_bfloat16* pA = (pass == 1) ? sAl : sAh;
            const __nv_bfloat16* pB = (pass == 2) ? sBl : sBh;
            #pragma unroll
            for (int kk = 0; kk < KC / 16; ++kk) {
                wmma::fragment<wmma::matrix_a, 16, 16, 16, __nv_bfloat16, wmma::row_major> af[2];
                wmma::fragment<wmma::matrix_b, 16, 16, 16, __nv_bfloat16, wmma::col_major> bf[2];
                #pragma unroll
                for (int i = 0; i < 2; ++i)
                    wmma::load_matrix_sync(af[i], &pA[(wr * 32 + i * 16) * LDA + kk * 16], LDA);
                #pragma unroll
                for (int j = 0; j < 2; ++j)
                    wmma::load_matrix_sync(bf[j], &pB[(wc * 32 + j * 16) * LDB + kk * 16], LDB);
                #pragma unroll
                for (int i = 0; i < 2; ++i)
                    #pragma unroll
                    for (int j = 0; j < 2; ++j)
                        wmma::mma_sync(acc[i][j], af[i], bf[j], acc[i][j]);
            }
        }
    }

    __syncthreads();
    #pragma unroll
    for (int i = 0; i < 2; ++i)
        #pragma unroll
        for (int j = 0; j < 2; ++j)
            wmma::store_matrix_sync(&stage[(wr * 32 + i * 16) * LDST + wc * 32 + j * 16],
                                    acc[i][j], LDST, wmma::mem_row_major);
    __syncthreads();
    for (int i = tid; i < 128 * 64; i += 256) {
        int row = i >> 6, c = i & 63;
        int r = rowBase + row;
        if (!fullTile && r >= N_NODES) continue;
        Cout[(size_t)r * C_DIM + c] = stage[row * LDST + c] + bias[c];
    }
}

// ======================= launch: fork-join CSR chain alongside convert+fc1 =======================
extern "C" void kernel_launch(void* const* d_in, const int* in_sizes, int n_in,
                              void* d_out, int out_size) {
    const float* x     = (const float*)d_in[0];
    const float* fc1_w = (const float*)d_in[1];
    const float* fc1_b = (const float*)d_in[2];
    const float* W1    = (const float*)d_in[3];
    const float* W2    = (const float*)d_in[4];
    const float* bgc   = (const float*)d_in[5];
    const float* fc2_w = (const float*)d_in[6];
    const float* fc2_b = (const float*)d_in[7];
    const int*   src   = (const int*)d_in[8];
    const int*   dst   = (const int*)d_in[9];
    float*       out   = (float*)d_out;

    const int TPB = 256;
    const int nodeBlocks = (N_NODES + TPB - 1) / TPB;
    const int edgeBlocks = (E_EDGES + TPB - 1) / TPB;
    const int prepBlocks = (N_NODES * IN_DIM / 4 + TPB - 1) / TPB;
    const int TILES = N_PAD / 128;   // 313

    static cudaStream_t s2 = nullptr;
    static cudaEvent_t evFork = nullptr, evJoin = nullptr;
    if (s2 == nullptr) {
        cudaStreamCreateWithFlags(&s2, cudaStreamNonBlocking);
        cudaEventCreateWithFlags(&evFork, cudaEventDisableTiming);
        cudaEventCreateWithFlags(&evJoin, cudaEventDisableTiming);
    }

    // 0: init (both chains depend on it)
    init_kernel<<<nodeBlocks, TPB>>>();
    cudaEventRecord(evFork, 0);
    cudaStreamWaitEvent(s2, evFork, 0);

    // Chain B on s2: degree count -> scan -> fill
    prep_edges_kernel<<<edgeBlocks, TPB, 0, s2>>>(src, dst);
    scan1_kernel<<<SCAN_NB, SCAN_B, 0, s2>>>();
    scan23_kernel<<<nodeBlocks, TPB, 0, s2>>>();
    fill_kernel<<<edgeBlocks, TPB, 0, s2>>>(src, dst);
    cudaEventRecord(evJoin, s2);

    // Chain A on default: convert -> fc1
    prep_convert_kernel<<<prepBlocks, TPB>>>(x, fc1_w, W1, W2, fc2_w);
    gemm_tc<0><<<TILES, 256>>>(fc1_b, 0);

    // join: gathers need CSR + norms + h
    cudaStreamWaitEvent(0, evJoin, 0);

    const int gatherBlocks = (N_NODES * 32 + TPB - 1) / TPB;
    for (int l = 0; l < L_LAYERS; ++l) {
        gather_kernel<<<gatherBlocks, TPB>>>();
        gemm_tc<1><<<TILES, 256>>>(bgc + (size_t)l * H_DIM, l);
    }

    gemm_fc2<<<TILES, 256>>>(fc2_b, out);
}